// round 5
// baseline (speedup 1.0000x reference)
#include <cuda_runtime.h>
#include <cuda_bf16.h>

#define NN 100000
#define NE 1600000
#define CAP 64                // bucket capacity per node (max degree headroom)
#define DIN 256
#define DHID 64
#define DOUT 32

// ---------------- scratch (static device memory: allowed) ----------------
__device__ float  g_x0[NN * DOUT];
__device__ float  g_xa[NN * DOUT];
__device__ float  g_xb[NN * DOUT];
__device__ float2 g_cv[(size_t)NN * CAP];   // bucketed (col-as-int-bits, 0.9*val)
__device__ int    g_deg[NN];
__device__ int    g_bcnt[16];               // per-trip-count histogram
__device__ int    g_bbase[16];
__device__ int    g_bcur[16];
__device__ int    g_order[NN];              // nodes sorted by trip count

// ---------------- fill: bucketed scatter ----------------
__global__ void k_fill(const int* __restrict__ row, const int* __restrict__ col,
                       const float* __restrict__ val) {
    int e = blockIdx.x * blockDim.x + threadIdx.x;
    if (e < NE) {
        int r = row[e];
        int idx = atomicAdd(&g_deg[r], 1);
        g_cv[(size_t)r * CAP + idx] = make_float2(__int_as_float(col[e]), 0.9f * val[e]);
    }
}

// zero padding tail to multiple of 8 + build trip-count histogram
__global__ void k_pad() {
    int i = blockIdx.x * blockDim.x + threadIdx.x;
    if (i < NN) {
        int d = g_deg[i];
        int dp = (d + 7) & ~7;
        float2* b = &g_cv[(size_t)i * CAP];
        for (int p = d; p < dp; p++) b[p] = make_float2(0.f, 0.f);
        atomicAdd(&g_bcnt[dp >> 3], 1);
    }
}

// tiny exclusive scan over 16 buckets (1 warp)
__global__ void k_binscan() {
    if (threadIdx.x == 0) {
        int run = 0;
        for (int t = 0; t < 16; t++) {
            g_bbase[t] = run;
            g_bcur[t]  = run;
            run += g_bcnt[t];
        }
    }
}

// scatter node ids into trip-sorted order
__global__ void k_scatter() {
    int i = blockIdx.x * blockDim.x + threadIdx.x;
    if (i < NN) {
        int t = ((g_deg[i] + 7) & ~7) >> 3;
        int pos = atomicAdd(&g_bcur[t], 1);
        g_order[pos] = i;
    }
}

// ---------------- MLP head: x0 = relu(F@W1 + b1)@W2 + b2 ----------------
// Layer-1 inner product uses packed fma.rn.f32x2 (SASS FFMA2): W1 rows are read
// as ulonglong2 (reg pairs = packed f32x2 operands, no pack movs needed).
#define FPAD 33
__global__ void __launch_bounds__(256)
k_mlp(const float* __restrict__ features,
      const float* __restrict__ W1, const float* __restrict__ b1,
      const float* __restrict__ W2, const float* __restrict__ b2) {
    extern __shared__ float sm[];
    float* w1s = sm;                      // 16384
    float* w2s = sm + 16384;              // 2048
    float* b1s = w2s + 2048;              // 64
    float* b2s = b1s + 64;                // 32
    float* fsm = b2s + 32;                // 256*33 = 8448

    const int t = threadIdx.x;
    const int node0 = blockIdx.x * 256;

    // fused init for the CSR build that follows
    {
        int gt = node0 + t;
        if (gt < NN) g_deg[gt] = 0;
        if (blockIdx.x == 0 && t < 16) g_bcnt[t] = 0;
    }

    for (int i = t; i < DIN * DHID; i += 256) w1s[i] = W1[i];
    for (int i = t; i < DHID * DOUT; i += 256) w2s[i] = W2[i];
    if (t < DHID) b1s[t] = b1[t];
    if (t < DOUT) b2s[t] = b2[t];
    __syncthreads();

    const ulonglong2* w1u2 = (const ulonglong2*)w1s;   // 16 chunks of 16B per row
    const float4* w2s4 = (const float4*)w2s;

    unsigned long long accp[32];
    #pragma unroll
    for (int i = 0; i < 32; i++) accp[i] = 0ull;

    for (int c = 0; c < DIN / 32; c++) {
        const int k0 = c * 32;
        __syncthreads();
        #pragma unroll
        for (int r = 0; r < 8; r++) {
            int lin = r * 256 + t;
            int nd = lin >> 3;
            int kg = lin & 7;
            float4 f4 = make_float4(0.f, 0.f, 0.f, 0.f);
            if (node0 + nd < NN)
                f4 = *(const float4*)&features[(size_t)(node0 + nd) * DIN + k0 + kg * 4];
            float* dst = &fsm[nd * FPAD + kg * 4];
            dst[0] = f4.x; dst[1] = f4.y; dst[2] = f4.z; dst[3] = f4.w;
        }
        __syncthreads();

        #pragma unroll 4
        for (int kk = 0; kk < 32; kk++) {
            float f = fsm[t * FPAD + kk];
            unsigned long long ff;
            asm("mov.b64 %0, {%1, %1};" : "=l"(ff) : "f"(f));
            #pragma unroll
            for (int w = 0; w < 16; w++) {
                ulonglong2 wv = w1u2[(k0 + kk) * 16 + w];
                asm("fma.rn.f32x2 %0, %1, %2, %0;" : "+l"(accp[2 * w])     : "l"(wv.x), "l"(ff));
                asm("fma.rn.f32x2 %0, %1, %2, %0;" : "+l"(accp[2 * w + 1]) : "l"(wv.y), "l"(ff));
            }
        }
    }

    // unpack, bias + relu
    float acc[DHID];
    #pragma unroll
    for (int i = 0; i < 32; i++) {
        float lo, hi;
        asm("mov.b64 {%0, %1}, %2;" : "=f"(lo), "=f"(hi) : "l"(accp[i]));
        acc[2 * i]     = lo;
        acc[2 * i + 1] = hi;
    }
    #pragma unroll
    for (int i = 0; i < DHID; i++) {
        float z = acc[i] + b1s[i];
        acc[i] = z > 0.f ? z : 0.f;
    }

    for (int jg = 0; jg < 8; jg++) {
        float4 sv = ((const float4*)b2s)[jg];
        #pragma unroll
        for (int l = 0; l < DHID; l++) {
            float4 wv = w2s4[l * 8 + jg];
            float h = acc[l];
            sv.x += h * wv.x; sv.y += h * wv.y;
            sv.z += h * wv.z; sv.w += h * wv.w;
        }
        float* dst = &fsm[t * FPAD + jg * 4];
        dst[0] = sv.x; dst[1] = sv.y; dst[2] = sv.z; dst[3] = sv.w;
    }
    __syncthreads();

    #pragma unroll
    for (int r = 0; r < 8; r++) {
        int lin = r * 256 + t;
        int nd = lin >> 3;
        int jg = lin & 7;
        if (node0 + nd < NN) {
            float4 o;
            const float* src = &fsm[nd * FPAD + jg * 4];
            o.x = src[0]; o.y = src[1]; o.z = src[2]; o.w = src[3];
            *(float4*)&g_x0[(size_t)(node0 + nd) * DOUT + jg * 4] = o;
        }
    }
}

// ---------------- propagation: dst = (A' @ src) + 0.1 * x0  (0.9 folded into A') ------
// 4 trip-sorted nodes per warp (grp = lane>>3, lane8 = lane&7 → 32 cols via float4).
// Rolled trip loop with next-descriptor prefetch; sentinel edges gather row 0.
__global__ void __launch_bounds__(256, 7)
k_spmm(const float* __restrict__ xsrc, float* __restrict__ xdst) {
    int gtid  = blockIdx.x * blockDim.x + threadIdx.x;
    int warp  = gtid >> 5;
    int lane  = threadIdx.x & 31;
    int grp   = lane >> 3;
    int lane8 = lane & 7;
    int slot  = warp * 4 + grp;
    if (slot >= NN) return;
    int node = g_order[slot];            // trip-sorted → quad has (near-)equal trips

    int trip = (g_deg[node] + 7) >> 3;
    int mt = trip;
    mt = max(mt, __shfl_xor_sync(0xffffffffu, mt, 16));
    mt = max(mt, __shfl_xor_sync(0xffffffffu, mt, 8));

    const float2* __restrict__ bucket = &g_cv[(size_t)node * CAP];

    float4 acc = make_float4(0.f, 0.f, 0.f, 0.f);
    float2 cv = make_float2(0.f, 0.f);
    if (0 < trip) cv = __ldg(&bucket[lane8]);

    for (int t = 0; t < mt; t++) {
        float2 nv = make_float2(0.f, 0.f);
        if (t + 1 < trip) nv = __ldg(&bucket[lane8 + 8 * (t + 1)]);
        #pragma unroll
        for (int j = 0; j < 8; j++) {
            int   c = __float_as_int(__shfl_sync(0xffffffffu, cv.x, (lane & 24) + j));
            float v = __shfl_sync(0xffffffffu, cv.y, (lane & 24) + j);
            float4 g = __ldg((const float4*)&xsrc[(size_t)c * DOUT + lane8 * 4]);
            acc.x += v * g.x;
            acc.y += v * g.y;
            acc.z += v * g.z;
            acc.w += v * g.w;
        }
        cv = nv;
    }

    const float4 x0 = *(const float4*)&g_x0[(size_t)node * DOUT + lane8 * 4];
    float4 o;
    o.x = acc.x + 0.1f * x0.x;
    o.y = acc.y + 0.1f * x0.y;
    o.z = acc.z + 0.1f * x0.z;
    o.w = acc.w + 0.1f * x0.w;
    *(float4*)&xdst[(size_t)node * DOUT + lane8 * 4] = o;
}

// ---------------- launch ----------------
extern "C" void kernel_launch(void* const* d_in, const int* in_sizes, int n_in,
                              void* d_out, int out_size) {
    const float* features = (const float*)d_in[0];
    const int*   row      = (const int*)d_in[1];
    const int*   col      = (const int*)d_in[2];
    const float* vals     = (const float*)d_in[3];
    const float* W1       = (const float*)d_in[4];
    const float* b1       = (const float*)d_in[5];
    const float* W2       = (const float*)d_in[6];
    const float* b2       = (const float*)d_in[7];

    float *x0p, *xap, *xbp;
    cudaGetSymbolAddress((void**)&x0p, g_x0);
    cudaGetSymbolAddress((void**)&xap, g_xa);
    cudaGetSymbolAddress((void**)&xbp, g_xb);

    // 1) MLP head (also zeroes degree counters + bucket histogram)
    const int smem_bytes = (16384 + 2048 + 64 + 32 + 256 * FPAD) * sizeof(float);
    cudaFuncSetAttribute(k_mlp, cudaFuncAttributeMaxDynamicSharedMemorySize, smem_bytes);
    k_mlp<<<(NN + 255) / 256, 256, smem_bytes>>>(features, W1, b1, W2, b2);

    // 2) bucketed CSR build, pad, and trip-count sort
    k_fill<<<(NE + 255) / 256, 256>>>(row, col, vals);
    k_pad<<<(NN + 255) / 256, 256>>>();
    k_binscan<<<1, 32>>>();
    k_scatter<<<(NN + 255) / 256, 256>>>();

    // 10 propagation steps, ping-pong; last writes d_out
    const int spmm_blocks = (NN / 4 * 32 + 255) / 256;   // 4 nodes per warp
    const float* src = x0p;
    for (int it = 0; it < 10; it++) {
        float* dst = (it == 9) ? (float*)d_out : ((it % 2 == 0) ? xap : xbp);
        k_spmm<<<spmm_blocks, 256>>>(src, dst);
        src = dst;
    }
}